// round 16
// baseline (speedup 1.0000x reference)
#include <cuda_runtime.h>
#include <cuda_bf16.h>
#include <math.h>
#include <cstdint>

// ---------------------------------------------------------------------------
// AdaLoRAWithBase restructured:
//   out = x + x@base + sum_r t[b,r] * x_b[b,:,r],  t[b,r] = sum_c x[b,c]*x_a[b,c,r]
//   [x_a|x_b] = GELU(LN(ada)@W1+b1) @ W2 + b2
// R16: R15 + reduce3 fused into gemm2's TAIL behind a second all-resident grid
// barrier; each of the 128 CTAs does 1/128 of the epilogue (2 b-rows).
// Pipeline: prepass -> k13 -> gemm2(reduce1 prologue + mainloop + t + reduce3).
// ---------------------------------------------------------------------------

namespace {
constexpr int Bsz = 256;
constexpr int Dd  = 1024;
constexpr int Aa  = 1024;
constexpr int Rr  = 8;
constexpr int W2N = Dd * Rr * 2;     // 16384
constexpr int XBN = Dd * Rr;         // 8192 (x_b width)
constexpr int Kd  = 1024;

constexpr int BM = 128, BK = 32;
constexpr int PSTG = 3;
constexpr int A_ROWB = 80;           // bytes per A smem row (40 bf16)
}

// Scratch (device globals)
__device__ __align__(16) float g_w[(size_t)Bsz * XBN];   // 8 MB (x_b only)
__device__ __align__(16) float g_tp[32 * Bsz * Rr];      // per-CTA t partials
__device__ __align__(16) float g_p1[4 * Bsz * Dd];
__device__ __align__(16) float g_p3[4 * Bsz * Dd];
__device__ __align__(16) __nv_bfloat16 g_Chi[Bsz * Kd];
__device__ __align__(16) __nv_bfloat16 g_Clo[Bsz * Kd];
__device__ __align__(16) __nv_bfloat16 g_Ahi[Bsz * Kd];
__device__ __align__(16) __nv_bfloat16 g_Alo[Bsz * Kd];
__device__ __align__(16) __nv_bfloat16 g_Xhi[Bsz * Kd];
__device__ int g_bar1;               // gemm2 prologue barrier counter
__device__ int g_bar2;               // gemm2 tail barrier counter

// ---------------------------------------------------------------------------
// PTX helpers (baseline sm_80+)
// ---------------------------------------------------------------------------
__device__ __forceinline__ uint32_t smem_u32(const void* p) {
    uint32_t a;
    asm("{ .reg .u64 t; cvta.to.shared.u64 t, %1; cvt.u32.u64 %0, t; }" : "=r"(a) : "l"(p));
    return a;
}
__device__ __forceinline__ void cp_async16(uint32_t saddr, const void* gaddr) {
    asm volatile("cp.async.cg.shared.global [%0], [%1], 16;" :: "r"(saddr), "l"(gaddr) : "memory");
}
__device__ __forceinline__ void cp_commit() {
    asm volatile("cp.async.commit_group;" ::: "memory");
}
template <int N>
__device__ __forceinline__ void cp_wait() {
    asm volatile("cp.async.wait_group %0;" :: "n"(N) : "memory");
}
__device__ __forceinline__ void ldsm_x4(uint32_t& r0, uint32_t& r1, uint32_t& r2, uint32_t& r3,
                                        uint32_t addr) {
    asm volatile("ldmatrix.sync.aligned.m8n8.x4.shared.b16 {%0,%1,%2,%3}, [%4];"
                 : "=r"(r0), "=r"(r1), "=r"(r2), "=r"(r3) : "r"(addr));
}
__device__ __forceinline__ void ldsm_x4_trans(uint32_t& r0, uint32_t& r1, uint32_t& r2,
                                              uint32_t& r3, uint32_t addr) {
    asm volatile("ldmatrix.sync.aligned.m8n8.x4.trans.shared.b16 {%0,%1,%2,%3}, [%4];"
                 : "=r"(r0), "=r"(r1), "=r"(r2), "=r"(r3) : "r"(addr));
}
__device__ __forceinline__ void mma16816(float* c, uint32_t a0, uint32_t a1, uint32_t a2,
                                         uint32_t a3, uint32_t b0, uint32_t b1) {
    asm volatile(
        "mma.sync.aligned.m16n8k16.row.col.f32.bf16.bf16.f32 "
        "{%0,%1,%2,%3},{%4,%5,%6,%7},{%8,%9},{%0,%1,%2,%3};"
        : "+f"(c[0]), "+f"(c[1]), "+f"(c[2]), "+f"(c[3])
        : "r"(a0), "r"(a1), "r"(a2), "r"(a3), "r"(b0), "r"(b1));
}
// pack two fp32 -> bf16x2 (RN); a -> low half, b -> high half
__device__ __forceinline__ uint32_t bf16x2_rn(float a, float b) {
    uint32_t r;
    asm("cvt.rn.bf16x2.f32 %0, %2, %1;" : "=r"(r) : "f"(a), "f"(b));
    return r;
}

// ---------------------------------------------------------------------------
// Merged pre-pass: blocks [0,256) do LayerNorm rows; blocks [256,768) split x
// (hi only). Block 0 resets the gemm2 barrier counters.
// ---------------------------------------------------------------------------
__global__ void __launch_bounds__(256) prepass_kernel(
    const float* __restrict__ ada, const float* __restrict__ gamma,
    const float* __restrict__ beta, const float* __restrict__ x)
{
    if (blockIdx.x == 0 && threadIdx.x == 0) { g_bar1 = 0; g_bar2 = 0; }
    if (blockIdx.x < 256) {
        int b = blockIdx.x;
        const float* row = ada + (size_t)b * Aa;
        float s = 0.f, s2 = 0.f;
        for (int i = threadIdx.x; i < Aa; i += blockDim.x) {
            float v = row[i]; s += v; s2 += v * v;
        }
        #pragma unroll
        for (int o = 16; o; o >>= 1) {
            s  += __shfl_down_sync(0xFFFFFFFFu, s,  o);
            s2 += __shfl_down_sync(0xFFFFFFFFu, s2, o);
        }
        __shared__ float red0[8], red1[8], mv[2];
        int wid = threadIdx.x >> 5, lid = threadIdx.x & 31;
        if (lid == 0) { red0[wid] = s; red1[wid] = s2; }
        __syncthreads();
        if (threadIdx.x == 0) {
            float ts = 0.f, ts2 = 0.f;
            #pragma unroll
            for (int i = 0; i < 8; i++) { ts += red0[i]; ts2 += red1[i]; }
            float mu = ts * (1.f / Aa);
            float var = ts2 * (1.f / Aa) - mu * mu;
            mv[0] = mu; mv[1] = rsqrtf(var + 1e-5f);
        }
        __syncthreads();
        float mu = mv[0], rs = mv[1];
        for (int i = threadIdx.x; i < Aa; i += blockDim.x) {
            float v = (row[i] - mu) * rs * gamma[i] + beta[i];
            __nv_bfloat16 hi = __float2bfloat16(v);
            g_Chi[(size_t)b * Aa + i] = hi;
            g_Clo[(size_t)b * Aa + i] = __float2bfloat16(v - __bfloat162float(hi));
        }
    } else {
        int i = ((blockIdx.x - 256) * 256 + threadIdx.x) * 2;
        float v0 = x[i], v1 = x[i + 1];
        *reinterpret_cast<__nv_bfloat162*>(&g_Xhi[i]) =
            __halves2bfloat162(__float2bfloat16(v0), __float2bfloat16(v1));
    }
}

// ---------------------------------------------------------------------------
// Unified bf16 hi/lo MMA GEMM, fused fp32 B conversion, PSTG=3.
// 3-pass by default; per-problem 2-pass (drop A-lo).
// FUSE_T:  x_a-half CTAs compute t partials (no early return).
// FUSE_R1: prologue performs reduce1 slice + grid-wide spin barrier.
// FUSE_R3: tail performs reduce3 slice behind a second grid barrier.
// (Barriers safe: gemm2 grid = 128 CTAs at 1 CTA/SM on 148 SMs.)
// ---------------------------------------------------------------------------
template <int BN_, int N_, int NTHR>
__device__ __forceinline__ void load_grp(
    uint32_t sstage, const __nv_bfloat16* __restrict__ ahi,
    const __nv_bfloat16* __restrict__ alo, const float* __restrict__ Braw,
    int m0, int n0, int k0, int tid, bool load_alo)
{
    constexpr int RCHR = BN_ / 4;
    constexpr int TOT = 1024 + 8 * BN_;
    #pragma unroll
    for (int it = 0; it < TOT / NTHR; it++) {
        int idx = tid + it * NTHR;
        if (idx < 512) {
            int row = idx >> 2, ch = idx & 3;
            cp_async16(sstage + row * A_ROWB + ch * 16,
                       &ahi[(size_t)(m0 + row) * Kd + k0 + ch * 8]);
        } else if (idx < 1024) {
            if (load_alo) {
                int l = idx - 512, row = l >> 2, ch = l & 3;
                cp_async16(sstage + 10240 + row * A_ROWB + ch * 16,
                           &alo[(size_t)(m0 + row) * Kd + k0 + ch * 8]);
            }
        } else {
            int l = idx - 1024;
            int row = l / RCHR, ch = l % RCHR;
            cp_async16(sstage + 20480 + row * (BN_ * 4) + ch * 16,
                       &Braw[(size_t)(k0 + row) * N_ + n0 + ch * 4]);
        }
    }
    cp_commit();
}

template <int BN_, int NTHR>
__device__ __forceinline__ void conv_b(char* smem, uint32_t raw_off, uint32_t bb_off,
                                       uint32_t bb_half, int tid)
{
    constexpr int B_RL = BN_ + 8;
    constexpr int RC = 8 * BN_;
    #pragma unroll
    for (int i = 0; i < RC / NTHR; i++) {
        int c = tid + i * NTHR;
        float4 v = *reinterpret_cast<const float4*>(smem + raw_off + c * 16);
        int row = c / (BN_ / 4);
        int col = (c % (BN_ / 4)) * 4;
        uint32_t hi01 = bf16x2_rn(v.x, v.y);
        uint32_t hi23 = bf16x2_rn(v.z, v.w);
        float h0 = __uint_as_float(hi01 << 16);
        float h1 = __uint_as_float(hi01 & 0xFFFF0000u);
        float h2 = __uint_as_float(hi23 << 16);
        float h3 = __uint_as_float(hi23 & 0xFFFF0000u);
        uint32_t lo01 = bf16x2_rn(v.x - h0, v.y - h1);
        uint32_t lo23 = bf16x2_rn(v.z - h2, v.w - h3);
        uint32_t eoff = (uint32_t)(row * B_RL + col) * 2;
        *reinterpret_cast<uint2*>(smem + bb_off + eoff)           = make_uint2(hi01, hi23);
        *reinterpret_cast<uint2*>(smem + bb_off + bb_half + eoff) = make_uint2(lo01, lo23);
    }
}

template <int BN_, int SK, bool HAS_BIAS, int N_, int NWM, int NWN, bool DUAL,
          int MINB, bool FUSE_T, bool TWOPASS1, bool FUSE_R1, bool FUSE_R3>
__global__ void __launch_bounds__(NWM * NWN * 32, MINB) gemm_mma_kernel(
    const __nv_bfloat16* __restrict__ ahi0, const __nv_bfloat16* __restrict__ alo0,
    const float* __restrict__ Braw0, float* __restrict__ C0,
    const __nv_bfloat16* __restrict__ ahi1, const __nv_bfloat16* __restrict__ alo1,
    const float* __restrict__ Braw1, float* __restrict__ C1,
    const float* __restrict__ bias, const float* __restrict__ xsrc,
    const float* __restrict__ b1v, float* __restrict__ outp)
{
    constexpr int NTHR = NWM * NWN * 32;
    constexpr int WN   = BN_ / NWN;
    constexpr int NT   = WN / 8;
    constexpr int B_RL = BN_ + 8;
    constexpr int STG  = 20480 + 128 * BN_;
    constexpr int OFF_BBc = PSTG * STG;
    constexpr int BB_HALFc = 32 * B_RL * 2;
    constexpr int BB_SZc = 2 * BB_HALFc;
    constexpr int KITERS = Kd / SK / BK;

    extern __shared__ char smem[];
    uint32_t sb = smem_u32(smem);
    const int tid = threadIdx.x, lane = tid & 31, wid = tid >> 5;
    const int warp_m = wid / NWN, warp_n = wid % NWN;
    const int m0 = blockIdx.y * BM, n0 = blockIdx.x * BN_;

    // ---- FUSE_R1: reduce1 slice + grid-wide spin barrier (all-resident) ----
    if constexpr (FUSE_R1) {
        int cid = blockIdx.y * gridDim.x + blockIdx.x;       // 0..127
        int e = cid * (NTHR * 4) + tid * 4;                  // covers Bsz*Kd
        float4 s = *reinterpret_cast<const float4*>(&g_p1[e]);
        #pragma unroll
        for (int zz = 1; zz < 4; zz++) {
            float4 p = *reinterpret_cast<const float4*>(&g_p1[zz * (Bsz * Dd) + e]);
            s.x += p.x; s.y += p.y; s.z += p.z; s.w += p.w;
        }
        float4 bb = *reinterpret_cast<const float4*>(&b1v[e & (Dd - 1)]);
        float u[4] = {s.x + bb.x, s.y + bb.y, s.z + bb.z, s.w + bb.w};
        __nv_bfloat16 hi[4], lo[4];
        #pragma unroll
        for (int q = 0; q < 4; q++) {
            float g = 0.5f * u[q] * (1.f + erff(u[q] * 0.70710678118654752f));
            hi[q] = __float2bfloat16(g);
            lo[q] = __float2bfloat16(g - __bfloat162float(hi[q]));
        }
        *reinterpret_cast<__nv_bfloat162*>(&g_Ahi[e])     = __halves2bfloat162(hi[0], hi[1]);
        *reinterpret_cast<__nv_bfloat162*>(&g_Ahi[e + 2]) = __halves2bfloat162(hi[2], hi[3]);
        *reinterpret_cast<__nv_bfloat162*>(&g_Alo[e])     = __halves2bfloat162(lo[0], lo[1]);
        *reinterpret_cast<__nv_bfloat162*>(&g_Alo[e + 2]) = __halves2bfloat162(lo[2], lo[3]);
        __threadfence();
        __syncthreads();
        if (tid == 0) {
            atomicAdd(&g_bar1, 1);
            while (*reinterpret_cast<volatile int*>(&g_bar1) <
                   (int)(gridDim.x * gridDim.y)) { }
        }
        __syncthreads();
    }

    int z = blockIdx.z;
    const __nv_bfloat16* ahi = ahi0;
    const __nv_bfloat16* alo = alo0;
    const float* Braw = Braw0;
    float* C = C0;
    const bool threep = !(TWOPASS1 && DUAL && blockIdx.z >= SK);
    if (DUAL && z >= SK) {
        z -= SK; ahi = ahi1; alo = alo1; Braw = Braw1; C = C1;
    }
    const int kb = z * (Kd / SK);

    float acc[4][NT][4];
    #pragma unroll
    for (int i = 0; i < 4; i++)
        #pragma unroll
        for (int j = 0; j < NT; j++)
            #pragma unroll
            for (int r = 0; r < 4; r++) acc[i][j][r] = 0.f;

    float2 biasv[NT];
    if constexpr (HAS_BIAS) {
        #pragma unroll
        for (int nt = 0; nt < NT; nt++)
            biasv[nt] = *reinterpret_cast<const float2*>(
                &bias[n0 + warp_n * WN + nt * 8 + (lane & 3) * 2]);
    }

    load_grp<BN_, N_, NTHR>(sb, ahi, alo, Braw, m0, n0, kb, tid, threep);
    load_grp<BN_, N_, NTHR>(sb + STG, ahi, alo, Braw, m0, n0, kb + BK, tid, threep);

    cp_wait<1>();
    conv_b<BN_, NTHR>(smem, 20480, OFF_BBc, BB_HALFc, tid);

    const int a_row_in_tile = lane & 15;
    const int a_colblk = (lane >> 4) << 3;
    const int b_krow = (lane & 7) + ((lane >> 3) & 1) * 8;
    const int b_cofs = warp_n * WN + ((lane >> 4) & 1) * 8;

    for (int kt = 0; kt < KITERS; kt++) {
        cp_wait<0>();
        __syncthreads();

        if (kt + 2 < KITERS)
            load_grp<BN_, N_, NTHR>(sb + ((kt + 2) % PSTG) * STG, ahi, alo, Braw,
                                    m0, n0, kb + (kt + 2) * BK, tid, threep);
        if (kt + 1 < KITERS)
            conv_b<BN_, NTHR>(smem, ((kt + 1) % PSTG) * STG + 20480,
                              OFF_BBc + ((kt + 1) & 1) * BB_SZc, BB_HALFc, tid);

        uint32_t abase = sb + (kt % PSTG) * STG;
        uint32_t bbase = sb + OFF_BBc + (kt & 1) * BB_SZc;

        #pragma unroll
        for (int ks = 0; ks < 2; ks++) {
            uint32_t af[4][4], bf[NT][2], bl2[NT][2];
            #pragma unroll
            for (int mt = 0; mt < 4; mt++) {
                int row = warp_m * 64 + mt * 16 + a_row_in_tile;
                uint32_t off = (uint32_t)(row * 40 + ks * 16 + a_colblk) * 2;
                ldsm_x4(af[mt][0], af[mt][1], af[mt][2], af[mt][3], abase + off);
            }
            #pragma unroll
            for (int ntp = 0; ntp < NT / 2; ntp++) {
                uint32_t off = (uint32_t)((ks * 16 + b_krow) * B_RL + b_cofs + ntp * 16) * 2;
                ldsm_x4_trans(bf[2*ntp][0], bf[2*ntp][1], bf[2*ntp+1][0], bf[2*ntp+1][1],
                              bbase + off);
            }
            #pragma unroll
            for (int mt = 0; mt < 4; mt++)
                #pragma unroll
                for (int nt = 0; nt < NT; nt++)
                    mma16816(acc[mt][nt], af[mt][0], af[mt][1], af[mt][2], af[mt][3],
                             bf[nt][0], bf[nt][1]);
            #pragma unroll
            for (int ntp = 0; ntp < NT / 2; ntp++) {
                uint32_t off = (uint32_t)((ks * 16 + b_krow) * B_RL + b_cofs + ntp * 16) * 2;
                ldsm_x4_trans(bl2[2*ntp][0], bl2[2*ntp][1], bl2[2*ntp+1][0], bl2[2*ntp+1][1],
                              bbase + BB_HALFc + off);
            }
            #pragma unroll
            for (int mt = 0; mt < 4; mt++)
                #pragma unroll
                for (int nt = 0; nt < NT; nt++)
                    mma16816(acc[mt][nt], af[mt][0], af[mt][1], af[mt][2], af[mt][3],
                             bl2[nt][0], bl2[nt][1]);
            if (threep) {
                #pragma unroll
                for (int mt = 0; mt < 4; mt++) {
                    int row = warp_m * 64 + mt * 16 + a_row_in_tile;
                    uint32_t off = (uint32_t)(row * 40 + ks * 16 + a_colblk) * 2;
                    ldsm_x4(af[mt][0], af[mt][1], af[mt][2], af[mt][3],
                            abase + 10240 + off);
                }
                #pragma unroll
                for (int mt = 0; mt < 4; mt++)
                    #pragma unroll
                    for (int nt = 0; nt < NT; nt++)
                        mma16816(acc[mt][nt], af[mt][0], af[mt][1], af[mt][2], af[mt][3],
                                 bf[nt][0], bf[nt][1]);
            }
        }
    }

    if (FUSE_T && blockIdx.x < (XBN / BN_)) {
        // x_a half: t partials. Each nt fragment = one d, r=0..7.
        float* tpart = (float*)smem;                          // [NWN][128][8]
        float* x_s = (float*)(smem + NWN * 128 * 8 * 4);      // [128][32]
        __syncthreads();
        {
            int d0 = n0 / 8;
            int row = tid >> 2, ch = tid & 3;
            float4 v = *reinterpret_cast<const float4*>(
                &xsrc[(size_t)(m0 + row) * Dd + d0 + ch * 8]);
            float4 v2 = *reinterpret_cast<const float4*>(
                &xsrc[(size_t)(m0 + row) * Dd + d0 + ch * 8 + 4]);
            *reinterpret_cast<float4*>(&x_s[row * 32 + ch * 8]) = v;
            *reinterpret_cast<float4*>(&x_s[row * 32 + ch * 8 + 4]) = v2;
        }
        __syncthreads();

        int r0 = (lane & 3) * 2;
        #pragma unroll
        for (int mt = 0; mt < 4; mt++) {
            int row_a = warp_m * 64 + mt * 16 + (lane >> 2);
            int row_b = row_a + 8;
            float t00 = 0.f, t01 = 0.f, t10 = 0.f, t11 = 0.f;
            #pragma unroll
            for (int nt = 0; nt < NT; nt++) {
                int dl = warp_n * NT + nt;
                float xa = x_s[row_a * 32 + dl];
                float xb = x_s[row_b * 32 + dl];
                float bx = 0.f, by = 0.f;
                if constexpr (HAS_BIAS) { bx = biasv[nt].x; by = biasv[nt].y; }
                t00 += xa * (acc[mt][nt][0] + bx);
                t01 += xa * (acc[mt][nt][1] + by);
                t10 += xb * (acc[mt][nt][2] + bx);
                t11 += xb * (acc[mt][nt][3] + by);
            }
            tpart[(warp_n * 128 + row_a) * 8 + r0]     = t00;
            tpart[(warp_n * 128 + row_a) * 8 + r0 + 1] = t01;
            tpart[(warp_n * 128 + row_b) * 8 + r0]     = t10;
            tpart[(warp_n * 128 + row_b) * 8 + r0 + 1] = t11;
        }
        __syncthreads();
        #pragma unroll
        for (int i = 0; i < 2; i++) {
            int pr = tid + i * NTHR;
            int row = pr >> 3, r = pr & 7;
            float s = 0.f;
            #pragma unroll
            for (int w = 0; w < NWN; w++)
                s += tpart[(w * 128 + row) * 8 + r];
            g_tp[((size_t)blockIdx.x * Bsz + m0 + row) * Rr + r] = s;
        }
    } else {
        // normal / x_b store
        float* Cw;
        if constexpr (SK == 1) {
            Cw = C;
        } else {
            Cw = C + (size_t)z * Bsz * N_;
        }
        int nbase = n0;
        int nstride = N_;
        if constexpr (FUSE_T) { nbase = n0 - XBN; nstride = XBN; }
        #pragma unroll
        for (int mt = 0; mt < 4; mt++) {
            int row0 = m0 + warp_m * 64 + mt * 16 + (lane >> 2);
            #pragma unroll
            for (int nt = 0; nt < NT; nt++) {
                int col = nbase + warp_n * WN + nt * 8 + (lane & 3) * 2;
                float bx = 0.f, by = 0.f;
                if constexpr (HAS_BIAS) { bx = biasv[nt].x; by = biasv[nt].y; }
                float2 v0 = make_float2(acc[mt][nt][0] + bx, acc[mt][nt][1] + by);
                float2 v1 = make_float2(acc[mt][nt][2] + bx, acc[mt][nt][3] + by);
                *reinterpret_cast<float2*>(&Cw[(size_t)row0 * nstride + col]) = v0;
                *reinterpret_cast<float2*>(&Cw[(size_t)(row0 + 8) * nstride + col]) = v1;
            }
        }
    }

    // ---- FUSE_R3: reduce3 slice behind second all-resident grid barrier ----
    if constexpr (FUSE_R3) {
        __threadfence();
        __syncthreads();
        if (tid == 0) {
            atomicAdd(&g_bar2, 1);
            while (*reinterpret_cast<volatile int*>(&g_bar2) <
                   (int)(gridDim.x * gridDim.y)) { }
        }
        __syncthreads();

        int cid = blockIdx.y * gridDim.x + blockIdx.x;   // 0..127; 2 b-rows each
        float* t_s = (float*)smem;                       // [2][8]
        {
            // 16 warps <-> 16 (bloc, r) pairs; lanes = partial index p
            int bloc = wid >> 3;            // 0 or 1
            int r = wid & 7;
            int b = cid * 2 + bloc;
            float v = g_tp[((size_t)lane * Bsz + b) * Rr + r];
            #pragma unroll
            for (int o = 16; o; o >>= 1)
                v += __shfl_down_sync(0xFFFFFFFFu, v, o);
            if (lane == 0) t_s[bloc * 8 + r] = v;
        }
        __syncthreads();

        int bloc = tid >> 8;                // 0 or 1
        int col4 = (tid & 255) * 4;
        int b = cid * 2 + bloc;
        size_t e = (size_t)b * Dd + col4;
        float4 s = *reinterpret_cast<const float4*>(&xsrc[e]);
        float4 q0 = *reinterpret_cast<const float4*>(&g_p3[0 * (Bsz * Dd) + e]);
        float4 q1 = *reinterpret_cast<const float4*>(&g_p3[1 * (Bsz * Dd) + e]);
        float4 q2 = *reinterpret_cast<const float4*>(&g_p3[2 * (Bsz * Dd) + e]);
        float4 q3 = *reinterpret_cast<const float4*>(&g_p3[3 * (Bsz * Dd) + e]);
        const float* wb = &g_w[(size_t)b * XBN + (size_t)col4 * Rr];
        float4 w[8];
        #pragma unroll
        for (int i = 0; i < 8; i++)
            w[i] = *reinterpret_cast<const float4*>(wb + i * 4);

        float t0 = t_s[bloc*8+0], t1 = t_s[bloc*8+1], t2 = t_s[bloc*8+2], t3 = t_s[bloc*8+3];
        float t4 = t_s[bloc*8+4], t5 = t_s[bloc*8+5], t6 = t_s[bloc*8+6], t7 = t_s[bloc*8+7];
        float lr[4];
        #pragma unroll
        for (int i = 0; i < 4; i++) {
            float4 wa = w[i * 2], wbv = w[i * 2 + 1];
            lr[i] = t0*wa.x + t1*wa.y + t2*wa.z + t3*wa.w
                  + t4*wbv.x + t5*wbv.y + t6*wbv.z + t7*wbv.w;
        }
        float4 r;
        r.x = s.x + q0.x + q1.x + q2.x + q3.x + lr[0];
        r.y = s.y + q0.y + q1.y + q2.y + q3.y + lr[1];
        r.z = s.z + q0.z + q1.z + q2.z + q3.z + lr[2];
        r.w = s.w + q0.w + q1.w + q2.w + q3.w + lr[3];
        *reinterpret_cast<float4*>(&outp[e]) = r;
    }
}

// ---------------------------------------------------------------------------
extern "C" void kernel_launch(void* const* d_in, const int* in_sizes, int n_in,
                              void* d_out, int out_size)
{
    const float* x    = (const float*)d_in[0];
    const float* ada  = (const float*)d_in[1];
    const float* base = (const float*)d_in[2];
    const float* gam  = (const float*)d_in[3];
    const float* bet  = (const float*)d_in[4];
    const float* W1   = (const float*)d_in[5];
    const float* b1   = (const float*)d_in[6];
    const float* W2   = (const float*)d_in[7];
    const float* b2   = (const float*)d_in[8];
    float* out = (float*)d_out;

    constexpr int SMEM64  = 3 * (20480 + 128 * 64)  + 2 * (2 * 32 * 72 * 2);   // 104448
    constexpr int SMEM256 = 3 * (20480 + 128 * 256) + 2 * (2 * 32 * 264 * 2);  // 227328

    float *w_p, *p1_p, *p3_p;
    __nv_bfloat16 *chi_p, *clo_p, *ahi_p, *alo_p, *xhi_p;
    cudaGetSymbolAddress((void**)&w_p,  g_w);
    cudaGetSymbolAddress((void**)&p1_p, g_p1);
    cudaGetSymbolAddress((void**)&p3_p, g_p3);
    cudaGetSymbolAddress((void**)&chi_p, g_Chi);
    cudaGetSymbolAddress((void**)&clo_p, g_Clo);
    cudaGetSymbolAddress((void**)&ahi_p, g_Ahi);
    cudaGetSymbolAddress((void**)&alo_p, g_Alo);
    cudaGetSymbolAddress((void**)&xhi_p, g_Xhi);

    // k13: DUAL; problem 0 = gemm1 (3-pass), problem 1 = gemm3 (2-pass)
    auto k13 = gemm_mma_kernel<64, 4, false, 1024, 2, 4, true, 2, false, true,
                               false, false>;
    // gemm2: 3-pass; fused reduce1 prologue + t epilogue + reduce3 tail
    auto k2  = gemm_mma_kernel<256, 1, true, 16384, 2, 8, false, 1, true, false,
                               true, true>;

    cudaFuncSetAttribute((const void*)k13,
                         cudaFuncAttributeMaxDynamicSharedMemorySize, SMEM64);
    cudaFuncSetAttribute((const void*)k2,
                         cudaFuncAttributeMaxDynamicSharedMemorySize, SMEM256);

    // prepass: barrier resets + LN (256 blocks) + x hi-split (512 blocks)
    prepass_kernel<<<768, 256>>>(ada, gam, bet, x);

    // GEMM1 + GEMM3 fused: z<4 -> cond@W1 partials (3-pass),
    //                      z>=4 -> x@base partials (2-pass)
    k13<<<dim3(16, 2, 8), 256, SMEM64>>>(
        chi_p, clo_p, W1, p1_p,
        xhi_p, nullptr, base, p3_p, nullptr, nullptr, nullptr, nullptr);

    // GEMM2: reduce1 prologue + mainloop + t partials/x_b store + reduce3 tail
    k2<<<dim3(W2N / 256, Bsz / BM, 1), 512, SMEM256>>>(
        ahi_p, alo_p, W2, w_p,
        nullptr, nullptr, nullptr, nullptr, b2, x, b1, out);
}

// round 17
// speedup vs baseline: 1.0475x; 1.0475x over previous
#include <cuda_runtime.h>
#include <cuda_bf16.h>
#include <math.h>
#include <cstdint>

// ---------------------------------------------------------------------------
// AdaLoRAWithBase restructured:
//   out = x + x@base + sum_r t[b,r] * x_b[b,:,r],  t[b,r] = sum_c x[b,c]*x_a[b,c,r]
//   [x_a|x_b] = GELU(LN(ada)@W1+b1) @ W2 + b2
// R17 = R15 (session best, 108.6us): all GEMMs on mma.sync bf16 hi/lo
// (3-pass; gemm3 2-pass), fused fp32->bf16 B conversion in-pipeline,
// t fused into gemm2 epilogue, reduce1 fused into gemm2 prologue behind an
// all-resident grid barrier. R16's tail fusion reverted (regressed).
// ---------------------------------------------------------------------------

namespace {
constexpr int Bsz = 256;
constexpr int Dd  = 1024;
constexpr int Aa  = 1024;
constexpr int Rr  = 8;
constexpr int W2N = Dd * Rr * 2;     // 16384
constexpr int XBN = Dd * Rr;         // 8192 (x_b width)
constexpr int Kd  = 1024;

constexpr int BM = 128, BK = 32;
constexpr int PSTG = 3;
constexpr int A_ROWB = 80;           // bytes per A smem row (40 bf16)
}

// Scratch (device globals)
__device__ __align__(16) float g_w[(size_t)Bsz * XBN];   // 8 MB (x_b only)
__device__ __align__(16) float g_tp[32 * Bsz * Rr];      // per-CTA t partials
__device__ __align__(16) float g_p1[4 * Bsz * Dd];
__device__ __align__(16) float g_p3[4 * Bsz * Dd];
__device__ __align__(16) __nv_bfloat16 g_Chi[Bsz * Kd];
__device__ __align__(16) __nv_bfloat16 g_Clo[Bsz * Kd];
__device__ __align__(16) __nv_bfloat16 g_Ahi[Bsz * Kd];
__device__ __align__(16) __nv_bfloat16 g_Alo[Bsz * Kd];
__device__ __align__(16) __nv_bfloat16 g_Xhi[Bsz * Kd];
__device__ int g_bar1;               // gemm2 prologue barrier counter

// ---------------------------------------------------------------------------
// PTX helpers (baseline sm_80+)
// ---------------------------------------------------------------------------
__device__ __forceinline__ uint32_t smem_u32(const void* p) {
    uint32_t a;
    asm("{ .reg .u64 t; cvta.to.shared.u64 t, %1; cvt.u32.u64 %0, t; }" : "=r"(a) : "l"(p));
    return a;
}
__device__ __forceinline__ void cp_async16(uint32_t saddr, const void* gaddr) {
    asm volatile("cp.async.cg.shared.global [%0], [%1], 16;" :: "r"(saddr), "l"(gaddr) : "memory");
}
__device__ __forceinline__ void cp_commit() {
    asm volatile("cp.async.commit_group;" ::: "memory");
}
template <int N>
__device__ __forceinline__ void cp_wait() {
    asm volatile("cp.async.wait_group %0;" :: "n"(N) : "memory");
}
__device__ __forceinline__ void ldsm_x4(uint32_t& r0, uint32_t& r1, uint32_t& r2, uint32_t& r3,
                                        uint32_t addr) {
    asm volatile("ldmatrix.sync.aligned.m8n8.x4.shared.b16 {%0,%1,%2,%3}, [%4];"
                 : "=r"(r0), "=r"(r1), "=r"(r2), "=r"(r3) : "r"(addr));
}
__device__ __forceinline__ void ldsm_x4_trans(uint32_t& r0, uint32_t& r1, uint32_t& r2,
                                              uint32_t& r3, uint32_t addr) {
    asm volatile("ldmatrix.sync.aligned.m8n8.x4.trans.shared.b16 {%0,%1,%2,%3}, [%4];"
                 : "=r"(r0), "=r"(r1), "=r"(r2), "=r"(r3) : "r"(addr));
}
__device__ __forceinline__ void mma16816(float* c, uint32_t a0, uint32_t a1, uint32_t a2,
                                         uint32_t a3, uint32_t b0, uint32_t b1) {
    asm volatile(
        "mma.sync.aligned.m16n8k16.row.col.f32.bf16.bf16.f32 "
        "{%0,%1,%2,%3},{%4,%5,%6,%7},{%8,%9},{%0,%1,%2,%3};"
        : "+f"(c[0]), "+f"(c[1]), "+f"(c[2]), "+f"(c[3])
        : "r"(a0), "r"(a1), "r"(a2), "r"(a3), "r"(b0), "r"(b1));
}
// pack two fp32 -> bf16x2 (RN); a -> low half, b -> high half
__device__ __forceinline__ uint32_t bf16x2_rn(float a, float b) {
    uint32_t r;
    asm("cvt.rn.bf16x2.f32 %0, %2, %1;" : "=r"(r) : "f"(a), "f"(b));
    return r;
}

// ---------------------------------------------------------------------------
// Merged pre-pass: blocks [0,256) do LayerNorm rows; blocks [256,768) split x
// (hi only). Block 0 resets the gemm2 barrier counter.
// ---------------------------------------------------------------------------
__global__ void __launch_bounds__(256) prepass_kernel(
    const float* __restrict__ ada, const float* __restrict__ gamma,
    const float* __restrict__ beta, const float* __restrict__ x)
{
    if (blockIdx.x == 0 && threadIdx.x == 0) g_bar1 = 0;
    if (blockIdx.x < 256) {
        int b = blockIdx.x;
        const float* row = ada + (size_t)b * Aa;
        float s = 0.f, s2 = 0.f;
        for (int i = threadIdx.x; i < Aa; i += blockDim.x) {
            float v = row[i]; s += v; s2 += v * v;
        }
        #pragma unroll
        for (int o = 16; o; o >>= 1) {
            s  += __shfl_down_sync(0xFFFFFFFFu, s,  o);
            s2 += __shfl_down_sync(0xFFFFFFFFu, s2, o);
        }
        __shared__ float red0[8], red1[8], mv[2];
        int wid = threadIdx.x >> 5, lid = threadIdx.x & 31;
        if (lid == 0) { red0[wid] = s; red1[wid] = s2; }
        __syncthreads();
        if (threadIdx.x == 0) {
            float ts = 0.f, ts2 = 0.f;
            #pragma unroll
            for (int i = 0; i < 8; i++) { ts += red0[i]; ts2 += red1[i]; }
            float mu = ts * (1.f / Aa);
            float var = ts2 * (1.f / Aa) - mu * mu;
            mv[0] = mu; mv[1] = rsqrtf(var + 1e-5f);
        }
        __syncthreads();
        float mu = mv[0], rs = mv[1];
        for (int i = threadIdx.x; i < Aa; i += blockDim.x) {
            float v = (row[i] - mu) * rs * gamma[i] + beta[i];
            __nv_bfloat16 hi = __float2bfloat16(v);
            g_Chi[(size_t)b * Aa + i] = hi;
            g_Clo[(size_t)b * Aa + i] = __float2bfloat16(v - __bfloat162float(hi));
        }
    } else {
        int i = ((blockIdx.x - 256) * 256 + threadIdx.x) * 2;
        float v0 = x[i], v1 = x[i + 1];
        *reinterpret_cast<__nv_bfloat162*>(&g_Xhi[i]) =
            __halves2bfloat162(__float2bfloat16(v0), __float2bfloat16(v1));
    }
}

// ---------------------------------------------------------------------------
// Unified bf16 hi/lo MMA GEMM, fused fp32 B conversion, PSTG=3.
// 3-pass by default; per-problem 2-pass (drop A-lo).
// FUSE_T: x_a-half CTAs compute t partials.
// FUSE_R1: prologue performs reduce1 slice + grid-wide spin barrier
//          (safe: gemm2 grid = 128 CTAs at 1 CTA/SM on 148 SMs).
// ---------------------------------------------------------------------------
template <int BN_, int N_, int NTHR>
__device__ __forceinline__ void load_grp(
    uint32_t sstage, const __nv_bfloat16* __restrict__ ahi,
    const __nv_bfloat16* __restrict__ alo, const float* __restrict__ Braw,
    int m0, int n0, int k0, int tid, bool load_alo)
{
    constexpr int RCHR = BN_ / 4;
    constexpr int TOT = 1024 + 8 * BN_;
    #pragma unroll
    for (int it = 0; it < TOT / NTHR; it++) {
        int idx = tid + it * NTHR;
        if (idx < 512) {
            int row = idx >> 2, ch = idx & 3;
            cp_async16(sstage + row * A_ROWB + ch * 16,
                       &ahi[(size_t)(m0 + row) * Kd + k0 + ch * 8]);
        } else if (idx < 1024) {
            if (load_alo) {
                int l = idx - 512, row = l >> 2, ch = l & 3;
                cp_async16(sstage + 10240 + row * A_ROWB + ch * 16,
                           &alo[(size_t)(m0 + row) * Kd + k0 + ch * 8]);
            }
        } else {
            int l = idx - 1024;
            int row = l / RCHR, ch = l % RCHR;
            cp_async16(sstage + 20480 + row * (BN_ * 4) + ch * 16,
                       &Braw[(size_t)(k0 + row) * N_ + n0 + ch * 4]);
        }
    }
    cp_commit();
}

template <int BN_, int NTHR>
__device__ __forceinline__ void conv_b(char* smem, uint32_t raw_off, uint32_t bb_off,
                                       uint32_t bb_half, int tid)
{
    constexpr int B_RL = BN_ + 8;
    constexpr int RC = 8 * BN_;
    #pragma unroll
    for (int i = 0; i < RC / NTHR; i++) {
        int c = tid + i * NTHR;
        float4 v = *reinterpret_cast<const float4*>(smem + raw_off + c * 16);
        int row = c / (BN_ / 4);
        int col = (c % (BN_ / 4)) * 4;
        uint32_t hi01 = bf16x2_rn(v.x, v.y);
        uint32_t hi23 = bf16x2_rn(v.z, v.w);
        float h0 = __uint_as_float(hi01 << 16);
        float h1 = __uint_as_float(hi01 & 0xFFFF0000u);
        float h2 = __uint_as_float(hi23 << 16);
        float h3 = __uint_as_float(hi23 & 0xFFFF0000u);
        uint32_t lo01 = bf16x2_rn(v.x - h0, v.y - h1);
        uint32_t lo23 = bf16x2_rn(v.z - h2, v.w - h3);
        uint32_t eoff = (uint32_t)(row * B_RL + col) * 2;
        *reinterpret_cast<uint2*>(smem + bb_off + eoff)           = make_uint2(hi01, hi23);
        *reinterpret_cast<uint2*>(smem + bb_off + bb_half + eoff) = make_uint2(lo01, lo23);
    }
}

template <int BN_, int SK, bool HAS_BIAS, int N_, int NWM, int NWN, bool DUAL,
          int MINB, bool FUSE_T, bool TWOPASS1, bool FUSE_R1>
__global__ void __launch_bounds__(NWM * NWN * 32, MINB) gemm_mma_kernel(
    const __nv_bfloat16* __restrict__ ahi0, const __nv_bfloat16* __restrict__ alo0,
    const float* __restrict__ Braw0, float* __restrict__ C0,
    const __nv_bfloat16* __restrict__ ahi1, const __nv_bfloat16* __restrict__ alo1,
    const float* __restrict__ Braw1, float* __restrict__ C1,
    const float* __restrict__ bias, const float* __restrict__ xsrc,
    const float* __restrict__ b1v)
{
    constexpr int NTHR = NWM * NWN * 32;
    constexpr int WN   = BN_ / NWN;
    constexpr int NT   = WN / 8;
    constexpr int B_RL = BN_ + 8;
    constexpr int STG  = 20480 + 128 * BN_;
    constexpr int OFF_BBc = PSTG * STG;
    constexpr int BB_HALFc = 32 * B_RL * 2;
    constexpr int BB_SZc = 2 * BB_HALFc;
    constexpr int KITERS = Kd / SK / BK;

    extern __shared__ char smem[];
    uint32_t sb = smem_u32(smem);
    const int tid = threadIdx.x, lane = tid & 31, wid = tid >> 5;
    const int warp_m = wid / NWN, warp_n = wid % NWN;
    const int m0 = blockIdx.y * BM, n0 = blockIdx.x * BN_;

    // ---- FUSE_R1: reduce1 slice + grid-wide spin barrier (all-resident) ----
    if constexpr (FUSE_R1) {
        int cid = blockIdx.y * gridDim.x + blockIdx.x;       // 0..127
        int e = cid * (NTHR * 4) + tid * 4;                  // covers Bsz*Kd
        float4 s = *reinterpret_cast<const float4*>(&g_p1[e]);
        #pragma unroll
        for (int zz = 1; zz < 4; zz++) {
            float4 p = *reinterpret_cast<const float4*>(&g_p1[zz * (Bsz * Dd) + e]);
            s.x += p.x; s.y += p.y; s.z += p.z; s.w += p.w;
        }
        float4 bb = *reinterpret_cast<const float4*>(&b1v[e & (Dd - 1)]);
        float u[4] = {s.x + bb.x, s.y + bb.y, s.z + bb.z, s.w + bb.w};
        __nv_bfloat16 hi[4], lo[4];
        #pragma unroll
        for (int q = 0; q < 4; q++) {
            float g = 0.5f * u[q] * (1.f + erff(u[q] * 0.70710678118654752f));
            hi[q] = __float2bfloat16(g);
            lo[q] = __float2bfloat16(g - __bfloat162float(hi[q]));
        }
        *reinterpret_cast<__nv_bfloat162*>(&g_Ahi[e])     = __halves2bfloat162(hi[0], hi[1]);
        *reinterpret_cast<__nv_bfloat162*>(&g_Ahi[e + 2]) = __halves2bfloat162(hi[2], hi[3]);
        *reinterpret_cast<__nv_bfloat162*>(&g_Alo[e])     = __halves2bfloat162(lo[0], lo[1]);
        *reinterpret_cast<__nv_bfloat162*>(&g_Alo[e + 2]) = __halves2bfloat162(lo[2], lo[3]);
        __threadfence();
        __syncthreads();
        if (tid == 0) {
            atomicAdd(&g_bar1, 1);
            while (*reinterpret_cast<volatile int*>(&g_bar1) <
                   (int)(gridDim.x * gridDim.y)) { }
        }
        __syncthreads();
    }

    int z = blockIdx.z;
    const __nv_bfloat16* ahi = ahi0;
    const __nv_bfloat16* alo = alo0;
    const float* Braw = Braw0;
    float* C = C0;
    const bool threep = !(TWOPASS1 && DUAL && blockIdx.z >= SK);
    if (DUAL && z >= SK) {
        z -= SK; ahi = ahi1; alo = alo1; Braw = Braw1; C = C1;
    }
    const int kb = z * (Kd / SK);

    float acc[4][NT][4];
    #pragma unroll
    for (int i = 0; i < 4; i++)
        #pragma unroll
        for (int j = 0; j < NT; j++)
            #pragma unroll
            for (int r = 0; r < 4; r++) acc[i][j][r] = 0.f;

    float2 biasv[NT];
    if constexpr (HAS_BIAS) {
        #pragma unroll
        for (int nt = 0; nt < NT; nt++)
            biasv[nt] = *reinterpret_cast<const float2*>(
                &bias[n0 + warp_n * WN + nt * 8 + (lane & 3) * 2]);
    }

    load_grp<BN_, N_, NTHR>(sb, ahi, alo, Braw, m0, n0, kb, tid, threep);
    load_grp<BN_, N_, NTHR>(sb + STG, ahi, alo, Braw, m0, n0, kb + BK, tid, threep);

    cp_wait<1>();
    conv_b<BN_, NTHR>(smem, 20480, OFF_BBc, BB_HALFc, tid);

    const int a_row_in_tile = lane & 15;
    const int a_colblk = (lane >> 4) << 3;
    const int b_krow = (lane & 7) + ((lane >> 3) & 1) * 8;
    const int b_cofs = warp_n * WN + ((lane >> 4) & 1) * 8;

    for (int kt = 0; kt < KITERS; kt++) {
        cp_wait<0>();
        __syncthreads();

        if (kt + 2 < KITERS)
            load_grp<BN_, N_, NTHR>(sb + ((kt + 2) % PSTG) * STG, ahi, alo, Braw,
                                    m0, n0, kb + (kt + 2) * BK, tid, threep);
        if (kt + 1 < KITERS)
            conv_b<BN_, NTHR>(smem, ((kt + 1) % PSTG) * STG + 20480,
                              OFF_BBc + ((kt + 1) & 1) * BB_SZc, BB_HALFc, tid);

        uint32_t abase = sb + (kt % PSTG) * STG;
        uint32_t bbase = sb + OFF_BBc + (kt & 1) * BB_SZc;

        #pragma unroll
        for (int ks = 0; ks < 2; ks++) {
            uint32_t af[4][4], bf[NT][2], bl2[NT][2];
            #pragma unroll
            for (int mt = 0; mt < 4; mt++) {
                int row = warp_m * 64 + mt * 16 + a_row_in_tile;
                uint32_t off = (uint32_t)(row * 40 + ks * 16 + a_colblk) * 2;
                ldsm_x4(af[mt][0], af[mt][1], af[mt][2], af[mt][3], abase + off);
            }
            #pragma unroll
            for (int ntp = 0; ntp < NT / 2; ntp++) {
                uint32_t off = (uint32_t)((ks * 16 + b_krow) * B_RL + b_cofs + ntp * 16) * 2;
                ldsm_x4_trans(bf[2*ntp][0], bf[2*ntp][1], bf[2*ntp+1][0], bf[2*ntp+1][1],
                              bbase + off);
            }
            #pragma unroll
            for (int mt = 0; mt < 4; mt++)
                #pragma unroll
                for (int nt = 0; nt < NT; nt++)
                    mma16816(acc[mt][nt], af[mt][0], af[mt][1], af[mt][2], af[mt][3],
                             bf[nt][0], bf[nt][1]);
            #pragma unroll
            for (int ntp = 0; ntp < NT / 2; ntp++) {
                uint32_t off = (uint32_t)((ks * 16 + b_krow) * B_RL + b_cofs + ntp * 16) * 2;
                ldsm_x4_trans(bl2[2*ntp][0], bl2[2*ntp][1], bl2[2*ntp+1][0], bl2[2*ntp+1][1],
                              bbase + BB_HALFc + off);
            }
            #pragma unroll
            for (int mt = 0; mt < 4; mt++)
                #pragma unroll
                for (int nt = 0; nt < NT; nt++)
                    mma16816(acc[mt][nt], af[mt][0], af[mt][1], af[mt][2], af[mt][3],
                             bl2[nt][0], bl2[nt][1]);
            if (threep) {
                #pragma unroll
                for (int mt = 0; mt < 4; mt++) {
                    int row = warp_m * 64 + mt * 16 + a_row_in_tile;
                    uint32_t off = (uint32_t)(row * 40 + ks * 16 + a_colblk) * 2;
                    ldsm_x4(af[mt][0], af[mt][1], af[mt][2], af[mt][3],
                            abase + 10240 + off);
                }
                #pragma unroll
                for (int mt = 0; mt < 4; mt++)
                    #pragma unroll
                    for (int nt = 0; nt < NT; nt++)
                        mma16816(acc[mt][nt], af[mt][0], af[mt][1], af[mt][2], af[mt][3],
                                 bf[nt][0], bf[nt][1]);
            }
        }
    }

    if (FUSE_T && blockIdx.x < (XBN / BN_)) {
        // x_a half: t partials. Each nt fragment = one d, r=0..7.
        float* tpart = (float*)smem;                          // [NWN][128][8]
        float* x_s = (float*)(smem + NWN * 128 * 8 * 4);      // [128][32]
        __syncthreads();
        {
            int d0 = n0 / 8;
            int row = tid >> 2, ch = tid & 3;
            float4 v = *reinterpret_cast<const float4*>(
                &xsrc[(size_t)(m0 + row) * Dd + d0 + ch * 8]);
            float4 v2 = *reinterpret_cast<const float4*>(
                &xsrc[(size_t)(m0 + row) * Dd + d0 + ch * 8 + 4]);
            *reinterpret_cast<float4*>(&x_s[row * 32 + ch * 8]) = v;
            *reinterpret_cast<float4*>(&x_s[row * 32 + ch * 8 + 4]) = v2;
        }
        __syncthreads();

        int r0 = (lane & 3) * 2;
        #pragma unroll
        for (int mt = 0; mt < 4; mt++) {
            int row_a = warp_m * 64 + mt * 16 + (lane >> 2);
            int row_b = row_a + 8;
            float t00 = 0.f, t01 = 0.f, t10 = 0.f, t11 = 0.f;
            #pragma unroll
            for (int nt = 0; nt < NT; nt++) {
                int dl = warp_n * NT + nt;
                float xa = x_s[row_a * 32 + dl];
                float xb = x_s[row_b * 32 + dl];
                float bx = 0.f, by = 0.f;
                if constexpr (HAS_BIAS) { bx = biasv[nt].x; by = biasv[nt].y; }
                t00 += xa * (acc[mt][nt][0] + bx);
                t01 += xa * (acc[mt][nt][1] + by);
                t10 += xb * (acc[mt][nt][2] + bx);
                t11 += xb * (acc[mt][nt][3] + by);
            }
            tpart[(warp_n * 128 + row_a) * 8 + r0]     = t00;
            tpart[(warp_n * 128 + row_a) * 8 + r0 + 1] = t01;
            tpart[(warp_n * 128 + row_b) * 8 + r0]     = t10;
            tpart[(warp_n * 128 + row_b) * 8 + r0 + 1] = t11;
        }
        __syncthreads();
        #pragma unroll
        for (int i = 0; i < 2; i++) {
            int pr = tid + i * NTHR;
            int row = pr >> 3, r = pr & 7;
            float s = 0.f;
            #pragma unroll
            for (int w = 0; w < NWN; w++)
                s += tpart[(w * 128 + row) * 8 + r];
            g_tp[((size_t)blockIdx.x * Bsz + m0 + row) * Rr + r] = s;
        }
        return;
    }

    // normal / x_b store
    float* Cw;
    if constexpr (SK == 1) {
        Cw = C;
    } else {
        Cw = C + (size_t)z * Bsz * N_;
    }
    int nbase = n0;
    int nstride = N_;
    if constexpr (FUSE_T) { nbase = n0 - XBN; nstride = XBN; }
    #pragma unroll
    for (int mt = 0; mt < 4; mt++) {
        int row0 = m0 + warp_m * 64 + mt * 16 + (lane >> 2);
        #pragma unroll
        for (int nt = 0; nt < NT; nt++) {
            int col = nbase + warp_n * WN + nt * 8 + (lane & 3) * 2;
            float bx = 0.f, by = 0.f;
            if constexpr (HAS_BIAS) { bx = biasv[nt].x; by = biasv[nt].y; }
            float2 v0 = make_float2(acc[mt][nt][0] + bx, acc[mt][nt][1] + by);
            float2 v1 = make_float2(acc[mt][nt][2] + bx, acc[mt][nt][3] + by);
            *reinterpret_cast<float2*>(&Cw[(size_t)row0 * nstride + col]) = v0;
            *reinterpret_cast<float2*>(&Cw[(size_t)(row0 + 8) * nstride + col]) = v1;
        }
    }
}

// ---------------------------------------------------------------------------
// reduce3: out = x + sum_z p3[z] + rank-8 epilogue; one block per b.
// ---------------------------------------------------------------------------
__global__ void __launch_bounds__(256) reduce3_kernel(
    const float* __restrict__ x, float* __restrict__ out)
{
    int b = blockIdx.x;
    __shared__ float t_s[Rr];
    {
        int p = threadIdx.x & 31, r = threadIdx.x >> 5;
        float v = g_tp[((size_t)p * Bsz + b) * Rr + r];
        #pragma unroll
        for (int o = 16; o; o >>= 1)
            v += __shfl_down_sync(0xFFFFFFFFu, v, o);
        if (p == 0) t_s[r] = v;
    }
    __syncthreads();

    int o = threadIdx.x * 4;
    size_t e = (size_t)b * Dd + o;
    float4 s = *reinterpret_cast<const float4*>(&x[e]);
    float4 q0 = *reinterpret_cast<const float4*>(&g_p3[0 * (Bsz * Dd) + e]);
    float4 q1 = *reinterpret_cast<const float4*>(&g_p3[1 * (Bsz * Dd) + e]);
    float4 q2 = *reinterpret_cast<const float4*>(&g_p3[2 * (Bsz * Dd) + e]);
    float4 q3 = *reinterpret_cast<const float4*>(&g_p3[3 * (Bsz * Dd) + e]);
    const float* wb = &g_w[(size_t)b * XBN + (size_t)o * Rr];
    float4 w[8];
    #pragma unroll
    for (int i = 0; i < 8; i++)
        w[i] = *reinterpret_cast<const float4*>(wb + i * 4);

    float t0 = t_s[0], t1 = t_s[1], t2 = t_s[2], t3 = t_s[3];
    float t4 = t_s[4], t5 = t_s[5], t6 = t_s[6], t7 = t_s[7];
    float lr[4];
    #pragma unroll
    for (int i = 0; i < 4; i++) {
        float4 wa = w[i * 2], wbv = w[i * 2 + 1];
        lr[i] = t0*wa.x + t1*wa.y + t2*wa.z + t3*wa.w
              + t4*wbv.x + t5*wbv.y + t6*wbv.z + t7*wbv.w;
    }
    float4 r;
    r.x = s.x + q0.x + q1.x + q2.x + q3.x + lr[0];
    r.y = s.y + q0.y + q1.y + q2.y + q3.y + lr[1];
    r.z = s.z + q0.z + q1.z + q2.z + q3.z + lr[2];
    r.w = s.w + q0.w + q1.w + q2.w + q3.w + lr[3];
    *reinterpret_cast<float4*>(&out[e]) = r;
}

// ---------------------------------------------------------------------------
extern "C" void kernel_launch(void* const* d_in, const int* in_sizes, int n_in,
                              void* d_out, int out_size)
{
    const float* x    = (const float*)d_in[0];
    const float* ada  = (const float*)d_in[1];
    const float* base = (const float*)d_in[2];
    const float* gam  = (const float*)d_in[3];
    const float* bet  = (const float*)d_in[4];
    const float* W1   = (const float*)d_in[5];
    const float* b1   = (const float*)d_in[6];
    const float* W2   = (const float*)d_in[7];
    const float* b2   = (const float*)d_in[8];
    float* out = (float*)d_out;

    constexpr int SMEM64  = 3 * (20480 + 128 * 64)  + 2 * (2 * 32 * 72 * 2);   // 104448
    constexpr int SMEM256 = 3 * (20480 + 128 * 256) + 2 * (2 * 32 * 264 * 2);  // 227328

    float *w_p, *p1_p, *p3_p;
    __nv_bfloat16 *chi_p, *clo_p, *ahi_p, *alo_p, *xhi_p;
    cudaGetSymbolAddress((void**)&w_p,  g_w);
    cudaGetSymbolAddress((void**)&p1_p, g_p1);
    cudaGetSymbolAddress((void**)&p3_p, g_p3);
    cudaGetSymbolAddress((void**)&chi_p, g_Chi);
    cudaGetSymbolAddress((void**)&clo_p, g_Clo);
    cudaGetSymbolAddress((void**)&ahi_p, g_Ahi);
    cudaGetSymbolAddress((void**)&alo_p, g_Alo);
    cudaGetSymbolAddress((void**)&xhi_p, g_Xhi);

    // k13: DUAL; problem 0 = gemm1 (3-pass), problem 1 = gemm3 (2-pass)
    auto k13 = gemm_mma_kernel<64, 4, false, 1024, 2, 4, true, 2, false, true, false>;
    // gemm2: 3-pass, fused t epilogue + fused reduce1 prologue
    auto k2  = gemm_mma_kernel<256, 1, true, 16384, 2, 8, false, 1, true, false, true>;

    cudaFuncSetAttribute((const void*)k13,
                         cudaFuncAttributeMaxDynamicSharedMemorySize, SMEM64);
    cudaFuncSetAttribute((const void*)k2,
                         cudaFuncAttributeMaxDynamicSharedMemorySize, SMEM256);

    // prepass: barrier reset + LN (256 blocks) + x hi-split (512 blocks)
    prepass_kernel<<<768, 256>>>(ada, gam, bet, x);

    // GEMM1 + GEMM3 fused: z<4 -> cond@W1 partials (3-pass),
    //                      z>=4 -> x@base partials (2-pass)
    k13<<<dim3(16, 2, 8), 256, SMEM64>>>(
        chi_p, clo_p, W1, p1_p,
        xhi_p, nullptr, base, p3_p, nullptr, nullptr, nullptr);

    // GEMM2: reduce1 fused in prologue (grid-wide barrier, all CTAs resident);
    // x_a half -> t partials, x_b -> g_w
    k2<<<dim3(W2N / 256, Bsz / BM, 1), 512, SMEM256>>>(
        ahi_p, alo_p, W2, w_p,
        nullptr, nullptr, nullptr, nullptr, b2, x, b1);

    // final epilogue
    reduce3_kernel<<<Bsz, 256>>>(x, out);
}